// round 8
// baseline (speedup 1.0000x reference)
#include <cuda_runtime.h>

// Grouped shifted conv:
//   t = roll(x, +1, axis=W); tp = zero-pad t by 1 on W
//   y[o*16+k, n, m] = sum_{i<64, j<3} tp[o*64+i, n, m+j] * W[i,k,j]
//   out[c, n, m] = y[c, (n-1)%56, m]   (roll +1 along H)
//
// Grid (56, 2, 2): one CTA per (input row n', group o, m-half), 448 threads.
// After ONE staging barrier, each warp is fully autonomous:
//   lane = 4*outputIdx + s, s = i-slice (16 channels each).
//   Per-lane partial over its slice, then 2x shfl.bfly reduces over s,
//   lanes with s==0 store a float4. No psum shared, no second barrier.
// ts rows interleaved pr = ii*4 + s (stride 36) so the 4 s-lanes of an
// output hit distinct banks; W padded by +(i>>4) so same-(ii,k) lanes
// broadcast.

#define NTHREADS 448
#define RSTRIDE  36

__global__ __launch_bounds__(NTHREADS) void shiftconv_kernel(
    const float* __restrict__ x,   // (128, 56, 56)
    const float* __restrict__ W,   // (64, 16, 3)
    float* __restrict__ out)       // (32, 56, 56)
{
    __shared__ float  ts[64 * RSTRIDE];    // row pr = (i&15)*4 + (i>>4), cols 0..29 used
    __shared__ float4 Ws4[64 * 16 + 4];    // entry i*16 + k + (i>>4)

    const int np  = blockIdx.x;            // input H-row n'
    const int o   = blockIdx.y;            // channel group
    const int mh  = blockIdx.z;            // m half: 0 -> cols [0,28), 1 -> [28,56)
    const int tid = threadIdx.x;

    // ---- Stage W (1024 entries over 448 threads) ----
    for (int e = tid; e < 1024; e += NTHREADS) {
        const int i = e >> 4;
        const float* wp = W + e * 3;       // row-major (64,16,3): (i*16+k)*3
        Ws4[e + (i >> 4)] = make_float4(wp[0], wp[1], wp[2], 0.0f);
    }

    // ---- Stage x m-window. row[c] = tp[c + 28*mh], tp[p] = x[p-2] (p in [2,57]),
    //      tp[1] = x[55] (wrap), tp[0] = tp[57] = 0. ----
    {
        const int row = tid / 7;           // 0..63
        const int q   = tid - row * 7;     // 0..6
        const int pr  = ((row & 15) << 2) | (row >> 4);
        const float* xr = x + (o * 64 + row) * 3136 + np * 56;
        float* d = &ts[pr * RSTRIDE];
        if (mh == 0) {
            // quads: c = w+2 for w in [0,28)
            const int w0 = q * 4;
            const float4 v = *(const float4*)(xr + w0);
            *(float2*)(d + w0 + 2) = make_float2(v.x, v.y);
            *(float2*)(d + w0 + 4) = make_float2(v.z, v.w);
        } else {
            // quads: c = w-26 for w in [26,55); c29 = 0 pad
            const int w0 = 28 + q * 4;
            const float4 v = *(const float4*)(xr + w0);
            if (q < 6) {
                const int c0 = w0 - 26;    // even
                *(float2*)(d + c0)     = make_float2(v.x, v.y);
                *(float2*)(d + c0 + 2) = make_float2(v.z, v.w);
            } else {
                d[26] = v.x; d[27] = v.y; d[28] = v.z; d[29] = 0.0f;
            }
        }
    }
    if (tid < 64) {
        const int pr = ((tid & 15) << 2) | (tid >> 4);
        float* d = &ts[pr * RSTRIDE];
        const float* xr = x + (o * 64 + tid) * 3136 + np * 56;
        if (mh == 0) {
            d[0] = 0.0f;
            d[1] = xr[55];                 // tp[1] = t[0] = x[55]
        } else {
            const float2 v = *(const float2*)(xr + 26);
            d[0] = v.x; d[1] = v.y;        // c0 = x[26], c1 = x[27]
        }
    }
    __syncthreads();

    // ---- Compute: warp-local, no further barriers ----
    const int lane = tid & 31;
    const int warp = tid >> 5;             // 0..13
    const int s    = lane & 3;             // i-slice
    const int oi   = (warp << 3) + (lane >> 2);  // 0..111
    const int k    = oi / 7;
    const int mq   = oi - k * 7;
    const int m    = mq * 4;

    float a0 = 0.f, a1 = 0.f, a2 = 0.f, a3 = 0.f;
    #pragma unroll
    for (int ii = 0; ii < 16; ii++) {
        const float4 w = Ws4[((s * 16 + ii) << 4) + k + s];
        const float* row = &ts[(ii * 4 + s) * RSTRIDE + m];
        const float4 A = *(const float4*)(row);      // taps m..m+3
        const float2 C = *(const float2*)(row + 4);  // taps m+4, m+5
        a0 += A.x * w.x + A.y * w.y + A.z * w.z;
        a1 += A.y * w.x + A.z * w.y + A.w * w.z;
        a2 += A.z * w.x + A.w * w.y + C.x * w.z;
        a3 += A.w * w.x + C.x * w.y + C.y * w.z;
    }

    // Butterfly reduce over the 4 i-slices (lane bits 0-1).
    #pragma unroll
    for (int off = 1; off <= 2; off <<= 1) {
        a0 += __shfl_xor_sync(0xFFFFFFFFu, a0, off);
        a1 += __shfl_xor_sync(0xFFFFFFFFu, a1, off);
        a2 += __shfl_xor_sync(0xFFFFFFFFu, a2, off);
        a3 += __shfl_xor_sync(0xFFFFFFFFu, a3, off);
    }

    if (s == 0) {
        int nout = np + 1; if (nout >= 56) nout -= 56;   // output H-roll
        *reinterpret_cast<float4*>(
            out + (o * 16 + k) * 3136 + nout * 56 + mh * 28 + m) =
            make_float4(a0, a1, a2, a3);
    }
}

extern "C" void kernel_launch(void* const* d_in, const int* in_sizes, int n_in,
                              void* d_out, int out_size) {
    const float* x = (const float*)d_in[0];   // 128*56*56 = 401408
    const float* W = (const float*)d_in[1];   // 64*16*3   = 3072
    float* out     = (float*)d_out;           // 32*56*56  = 100352

    dim3 grid(56, 2, 2);
    shiftconv_kernel<<<grid, NTHREADS>>>(x, W, out);
}

// round 9
// speedup vs baseline: 1.3640x; 1.3640x over previous
#include <cuda_runtime.h>

// Grouped shifted conv:
//   t = roll(x, +1, axis=W); tp = zero-pad t by 1 on W
//   y[o*16+k, n, m] = sum_{i<64, j<3} tp[o*64+i, n, m+j] * W[i,k,j]
//   out[c, n, m] = y[c, (n-1)%56, m]   (roll +1 along H)
//
// Grid (28, 2, 2): one CTA per (row PAIR, group o, m-half). 112 CTAs =
// one balanced wave. Block 512 = 4 subgroups of 128; subgroup s owns input
// channels [16s,16s+16). Both rows' x loads are issued up front; row1's
// GMEM latency hides under row0's barrier+compute (double-buffered smem).
// Producers post per-row psums with bar.arrive and exit; subgroup 0
// computes both rows before consuming psums, so its bar.sync waits are
// nearly free.

#define NTHREADS 512
#define RSTRIDE  32

__global__ __launch_bounds__(NTHREADS) void shiftconv_kernel(
    const float* __restrict__ x,   // (128, 56, 56)
    const float* __restrict__ W,   // (64, 16, 3)
    float* __restrict__ out)       // (32, 56, 56)
{
    __shared__ float  ts[2][64 * RSTRIDE];  // double-buffered m-window, cols 0..29
    __shared__ float4 Ws4[64 * 16];         // W[i][k][0..2], .w unused
    __shared__ float4 psum[2][3 * 112];     // per-row partials from subgroups 1..3

    const int nb  = blockIdx.x;             // row pair: rows 2nb, 2nb+1
    const int o   = blockIdx.y;             // channel group
    const int mh  = blockIdx.z;             // m half: 0 -> cols [0,28), 1 -> [28,56)
    const int tid = threadIdx.x;
    const int s   = tid >> 7;               // subgroup 0..3
    const int tl  = tid & 127;
    const int ibase = s * 16;

    // ---- Per-thread staging plan (same for both rows) ----
    int il, q;                              // row-within-slice, quad
    if (mh == 0) {
        if (tl < 112) { il = tl / 7; q = tl - (tl / 7) * 7; }
        else          { il = tl - 112; q = -1; }           // edge thread
    } else {
        il = tl >> 3; q = tl & 7;
    }

    // ---- Issue BOTH rows' x loads up front ----
    const float* xbase = x + (o * 64 + ibase) * 3136 + nb * 112;  // np0 = 2nb
    float4 v[2];
    float  e[2];
    #pragma unroll
    for (int r = 0; r < 2; r++) {
        const float* xr = xbase + r * 56 + il * 3136;
        if (mh == 0) {
            if (q >= 0) v[r] = *(const float4*)(xr + q * 4);       // w0 = 4q
            else        e[r] = xr[55];                              // wrap source
        } else {
            v[r] = *(const float4*)(xr + 24 + q * 4);               // w0 = 24+4q
        }
    }

    // ---- Stage W slice for this subgroup (under x-load shadow) ----
    #pragma unroll
    for (int idx = tl; idx < 256; idx += 128) {
        const int eidx = ibase * 16 + idx;
        const float* wp = W + eidx * 3;      // row-major (64,16,3)
        Ws4[eidx] = make_float4(wp[0], wp[1], wp[2], 0.0f);
    }

    const int k  = tl / 7;                   // valid for tl < 112
    const int mq = tl - k * 7;
    const int m  = mq * 4;

    float4 acc[2];
    #pragma unroll
    for (int r = 0; r < 2; r++) {
        // ---- STS row r (roll folded in; see R5 layout) ----
        float* dbase = &ts[r][0];
        float* d = &dbase[(ibase + il) * RSTRIDE];
        if (mh == 0) {
            if (q >= 0) {
                const int w0 = q * 4;        // local col = w+2
                *(float2*)(d + w0 + 2) = make_float2(v[r].x, v[r].y);
                *(float2*)(d + w0 + 4) = make_float2(v[r].z, v[r].w);
            } else {
                d[0] = 0.0f;                 // tp[0] pad
                d[1] = e[r];                 // tp[1] = x[55]
            }
        } else {
            // local col c = w-26 for w in [26,55); c29 = 0 pad
            if (q == 0) {
                d[0] = v[r].z; d[1] = v[r].w;                 // w = 26,27
                d[29] = 0.0f;
            } else if (q == 7) {
                d[26] = v[r].x; d[27] = v[r].y; d[28] = v[r].z; // w = 52..54
            } else {
                const int c0 = (24 + q * 4) - 26;              // even
                *(float2*)(d + c0)     = make_float2(v[r].x, v[r].y);
                *(float2*)(d + c0 + 2) = make_float2(v[r].z, v[r].w);
            }
        }

        // ---- Subgroup-local barrier (4 warps) ----
        asm volatile("bar.sync %0, 128;" :: "r"(1 + s) : "memory");

        // ---- Compute partial over this subgroup's 16 channels ----
        float a0 = 0.f, a1 = 0.f, a2 = 0.f, a3 = 0.f;
        if (tl < 112) {
            #pragma unroll
            for (int ii = 0; ii < 16; ii++) {
                const int i = ibase + ii;
                const float4 w = Ws4[i * 16 + k];
                const float* row = &dbase[i * RSTRIDE + m];
                const float4 A = *(const float4*)(row);      // taps m..m+3
                const float2 C = *(const float2*)(row + 4);  // taps m+4, m+5
                a0 += A.x * w.x + A.y * w.y + A.z * w.z;
                a1 += A.y * w.x + A.z * w.y + A.w * w.z;
                a2 += A.z * w.x + A.w * w.y + C.x * w.z;
                a3 += A.w * w.x + C.x * w.y + C.y * w.z;
            }
        }
        acc[r] = make_float4(a0, a1, a2, a3);

        if (s > 0) {
            if (tl < 112) psum[r][(s - 1) * 112 + tl] = acc[r];
            asm volatile("bar.arrive %0, %1;" :: "r"(5 + r), "n"(NTHREADS) : "memory");
        }
    }

    if (s > 0) return;                       // producers done

    // ---- Subgroup 0: reduce + store both rows ----
    #pragma unroll
    for (int r = 0; r < 2; r++) {
        asm volatile("bar.sync %0, %1;" :: "r"(5 + r), "n"(NTHREADS) : "memory");
        if (tl < 112) {
            float4 a = acc[r];
            const float4 p0 = psum[r][tl];
            const float4 p1 = psum[r][112 + tl];
            const float4 p2 = psum[r][224 + tl];
            a.x += p0.x + p1.x + p2.x;
            a.y += p0.y + p1.y + p2.y;
            a.z += p0.z + p1.z + p2.z;
            a.w += p0.w + p1.w + p2.w;

            int nout = nb * 2 + r + 1;       // output H-roll
            if (nout >= 56) nout -= 56;
            *reinterpret_cast<float4*>(
                out + (o * 16 + k) * 3136 + nout * 56 + mh * 28 + m) = a;
        }
    }
}

extern "C" void kernel_launch(void* const* d_in, const int* in_sizes, int n_in,
                              void* d_out, int out_size) {
    const float* x = (const float*)d_in[0];   // 128*56*56 = 401408
    const float* W = (const float*)d_in[1];   // 64*16*3   = 3072
    float* out     = (float*)d_out;           // 32*56*56  = 100352

    dim3 grid(28, 2, 2);
    shiftconv_kernel<<<grid, NTHREADS>>>(x, W, out);
}

// round 10
// speedup vs baseline: 1.3690x; 1.0037x over previous
#include <cuda_runtime.h>

// Grouped shifted conv:
//   t = roll(x, +1, axis=W); tp = zero-pad t by 1 on W
//   y[o*16+k, n, m] = sum_{i<64, j<3} tp[o*64+i, n, m+j] * W[i,k,j]
//   out[c, n, m] = y[c, (n-1)%56, m]   (roll +1 along H)
//
// Grid (28, 2, 2): one CTA per (row PAIR, group o, m-half). 112 CTAs =
// one balanced wave. Block 1024 = 8 subgroups of 128; subgroup s owns 8
// input channels [8s, 8s+8) -> 8-iteration inner loop, 32 warps/SM.
// Both rows' x loads issued up front (row1 latency hides under row0's
// barrier+compute). Producers post per-row psums with bar.arrive and
// exit; subgroup 0 computes both rows before consuming psums.

#define NTHREADS 1024
#define RSTRIDE  32

__global__ __launch_bounds__(NTHREADS) void shiftconv_kernel(
    const float* __restrict__ x,   // (128, 56, 56)
    const float* __restrict__ W,   // (64, 16, 3)
    float* __restrict__ out)       // (32, 56, 56)
{
    __shared__ float  ts[2][64 * RSTRIDE];  // double-buffered m-window, cols 0..29
    __shared__ float4 Ws4[64 * 16];         // W[i][k][0..2], .w unused
    __shared__ float4 psum[2][7 * 112];     // per-row partials from subgroups 1..7

    const int nb  = blockIdx.x;             // row pair: rows 2nb, 2nb+1
    const int o   = blockIdx.y;             // channel group
    const int mh  = blockIdx.z;             // m half: 0 -> cols [0,28), 1 -> [28,56)
    const int tid = threadIdx.x;
    const int s   = tid >> 7;               // subgroup 0..7
    const int tl  = tid & 127;
    const int ibase = s * 8;                // 8 channels per subgroup

    // ---- Per-thread staging plan (same for both rows) ----
    int il = 0, q = -2;                     // row-within-slice, quad (-2 = idle)
    if (mh == 0) {
        if (tl < 56)       { il = tl / 7;  q = tl - (tl / 7) * 7; }
        else if (tl < 64)  { il = tl - 56; q = -1; }        // edge thread
    } else {
        if (tl < 64)       { il = tl >> 3; q = tl & 7; }
    }

    // ---- Issue BOTH rows' x loads up front ----
    const float* xbase = x + (o * 64 + ibase) * 3136 + nb * 112;  // np0 = 2nb
    float4 v[2];
    float  e[2];
    #pragma unroll
    for (int r = 0; r < 2; r++) {
        const float* xr = xbase + r * 56 + il * 3136;
        if (mh == 0) {
            if (q >= 0)      v[r] = *(const float4*)(xr + q * 4);   // w0 = 4q
            else if (q == -1) e[r] = xr[55];                         // wrap source
        } else {
            if (q >= 0)      v[r] = *(const float4*)(xr + 24 + q * 4);
        }
    }

    // ---- Stage W slice for this subgroup (8 channels x 16 k = 128 entries) ----
    {
        const int eidx = ibase * 16 + tl;    // one entry per thread
        const float* wp = W + eidx * 3;      // row-major (64,16,3)
        Ws4[eidx] = make_float4(wp[0], wp[1], wp[2], 0.0f);
    }

    const int k  = tl / 7;                   // valid for tl < 112
    const int mq = tl - k * 7;
    const int m  = mq * 4;

    float4 acc[2];
    #pragma unroll
    for (int r = 0; r < 2; r++) {
        // ---- STS row r (roll folded in) ----
        float* dbase = &ts[r][0];
        float* d = &dbase[(ibase + il) * RSTRIDE];
        if (mh == 0) {
            if (q >= 0) {
                const int w0 = q * 4;        // local col = w+2
                *(float2*)(d + w0 + 2) = make_float2(v[r].x, v[r].y);
                *(float2*)(d + w0 + 4) = make_float2(v[r].z, v[r].w);
            } else if (q == -1) {
                d[0] = 0.0f;                 // tp[0] pad
                d[1] = e[r];                 // tp[1] = x[55]
            }
        } else {
            // local col c = w-26 for w in [26,55); c29 = 0 pad
            if (q == 0) {
                d[0] = v[r].z; d[1] = v[r].w;                   // w = 26,27
                d[29] = 0.0f;
            } else if (q == 7) {
                d[26] = v[r].x; d[27] = v[r].y; d[28] = v[r].z; // w = 52..54
            } else if (q > 0) {
                const int c0 = q * 4 - 2;                        // even
                *(float2*)(d + c0)     = make_float2(v[r].x, v[r].y);
                *(float2*)(d + c0 + 2) = make_float2(v[r].z, v[r].w);
            }
        }

        // ---- Subgroup-local barrier (4 warps = 128 threads) ----
        asm volatile("bar.sync %0, 128;" :: "r"(1 + s) : "memory");

        // ---- Compute partial over this subgroup's 8 channels ----
        float a0 = 0.f, a1 = 0.f, a2 = 0.f, a3 = 0.f;
        if (tl < 112) {
            #pragma unroll
            for (int ii = 0; ii < 8; ii++) {
                const int i = ibase + ii;
                const float4 w = Ws4[i * 16 + k];
                const float* row = &dbase[i * RSTRIDE + m];
                const float4 A = *(const float4*)(row);      // taps m..m+3
                const float2 C = *(const float2*)(row + 4);  // taps m+4, m+5
                a0 += A.x * w.x + A.y * w.y + A.z * w.z;
                a1 += A.y * w.x + A.z * w.y + A.w * w.z;
                a2 += A.z * w.x + A.w * w.y + C.x * w.z;
                a3 += A.w * w.x + C.x * w.y + C.y * w.z;
            }
        }
        acc[r] = make_float4(a0, a1, a2, a3);

        if (s > 0) {
            if (tl < 112) psum[r][(s - 1) * 112 + tl] = acc[r];
            asm volatile("bar.arrive %0, %1;" :: "r"(9 + r), "n"(NTHREADS) : "memory");
        }
    }

    if (s > 0) return;                       // producers done

    // ---- Subgroup 0: reduce + store both rows ----
    #pragma unroll
    for (int r = 0; r < 2; r++) {
        asm volatile("bar.sync %0, %1;" :: "r"(9 + r), "n"(NTHREADS) : "memory");
        if (tl < 112) {
            float4 a = acc[r];
            #pragma unroll
            for (int j = 0; j < 7; j++) {
                const float4 p = psum[r][j * 112 + tl];
                a.x += p.x; a.y += p.y; a.z += p.z; a.w += p.w;
            }
            int nout = nb * 2 + r + 1;       // output H-roll
            if (nout >= 56) nout -= 56;
            *reinterpret_cast<float4*>(
                out + (o * 16 + k) * 3136 + nout * 56 + mh * 28 + m) = a;
        }
    }
}

extern "C" void kernel_launch(void* const* d_in, const int* in_sizes, int n_in,
                              void* d_out, int out_size) {
    const float* x = (const float*)d_in[0];   // 128*56*56 = 401408
    const float* W = (const float*)d_in[1];   // 64*16*3   = 3072
    float* out     = (float*)d_out;           // 32*56*56  = 100352

    dim3 grid(28, 2, 2);
    shiftconv_kernel<<<grid, NTHREADS>>>(x, W, out);
}